// round 15
// baseline (speedup 1.0000x reference)
#include <cuda_runtime.h>
#include <math.h>

#define KTOK 2048
#define DDIM 2048
#define NBATCH 16
#define MAXIT 50
#define EPSF 1e-8f
#define STEPSZ (0.1f / 2048.0f)

#define NBLK 128
#define NTHR 512
#define NWARP 16
#define ROWS 16                 // tokens per CTA, one row per warp
#define DSL (DDIM / NBLK)       // 16 d-elements per CTA slice
#define D4  (DDIM / 4)          // 512 float4

// smem: Xs[ROWS*DDIM] + Gs[DDIM] + red[32] + aux[96] + dotp[16*17]
#define SMEM_FLOATS (ROWS * DDIM + DDIM + 32 + 96 + 272)
#define SMEM_BYTES (SMEM_FLOATS * 4)

// ------------- global scratch (ZEROED-ON-EXIT invariant) ------------------
__device__ __align__(16) float g_m[DDIM];
__device__ __align__(16) float g_gA[3][DDIM];     // grad bank A (even CTAs)
__device__ __align__(16) float g_gB[3][DDIM];     // grad bank B (odd CTAs)
__device__ __align__(16) float4 g_sc[3];          // (slam, pG, 0, 0)
__device__ float g_viol;
__device__ unsigned g_cnt;          // monotonic barrier counter

__device__ __forceinline__ unsigned ld_rlx(const unsigned *p)
{
    unsigned v;
    asm volatile("ld.relaxed.gpu.b32 %0, [%1];" : "=r"(v) : "l"(p) : "memory");
    return v;
}

// ------------- counter grid barrier: 1 RED arrive + 1 poller per CTA -----
__device__ __forceinline__ void grid_bar(unsigned target)
{
    __syncthreads();
    if (threadIdx.x == 0) {
        __threadfence();                  // release
        atomicAdd(&g_cnt, 1u);
        while (ld_rlx(&g_cnt) < target) {}
        __threadfence();                  // acquire
    }
    __syncthreads();
}

// deterministic block-wide sum: identical value on every thread & every CTA
__device__ __forceinline__ float block_sum(float v, float *red)
{
#pragma unroll
    for (int o = 16; o > 0; o >>= 1) v += __shfl_down_sync(0xffffffffu, v, o);
    __syncthreads();
    if ((threadIdx.x & 31) == 0) red[threadIdx.x >> 5] = v;
    __syncthreads();
    float s = red[0];
#pragma unroll
    for (int i = 1; i < NWARP; i++) s += red[i];
    __syncthreads();
    return s;
}

// log_map_at coefficients: v_k = -lam*p + mu*x_k, scalars only.
__device__ __forceinline__ void lam_mu(float dot, float xs, float p_sq,
                                       float &lam, float &mu)
{
    const float xy  = -dot;
    const float xsc = fminf(p_sq, 0.99f);
    const float ysc = fminf(xs, 0.99f);
    const float a   = 1.0f + 2.0f * xy + ysc;
    const float b   = 1.0f - xsc;
    const float den = fmaxf(1.0f + 2.0f * xy + xsc * ysc, EPSF);
    const float numsq = fmaxf(a * a * p_sq + b * b * xs - 2.0f * a * b * dot, 0.0f);
    const float rn  = sqrtf(numsq) / den;
    const float maxn = 1.0f - EPSF;
    const float c   = (rn >= maxn) ? (maxn - EPSF) / rn : 1.0f;
    const float n   = rn * c;
    const float s   = fminf(n, 1.0f - EPSF);
    const float scale = 2.0f * atanhf(s) / (n + EPSF);
    const float t   = (n < EPSF) ? 0.0f : scale * c / den;
    lam = t * a;
    mu  = t * b;
}

// float4 row-dot over SMEM (init phase only)
__device__ __forceinline__ float row_dot(const float4 *xr4, const float4 *vv4,
                                         int lane)
{
    float acc0 = 0.0f, acc1 = 0.0f;
#pragma unroll 4
    for (int j = 0; j < 16; j++) {
        const int d4 = lane + j * 32;
        float4 x = xr4[d4];
        float4 p = vv4[d4];
        acc0 += x.x * p.x + x.y * p.y;
        acc1 += x.z * p.z + x.w * p.w;
    }
    float p2 = acc0 + acc1;
#pragma unroll
    for (int o = 16; o > 0; o >>= 1) p2 += __shfl_down_sync(0xffffffffu, p2, o);
    return p2;   // valid on lane 0
}

__global__ void __launch_bounds__(NTHR, 1)
traj_kernel(const float *__restrict__ in, float *__restrict__ out)
{
    extern __shared__ float smem[];
    float *Xs   = smem;                 // [ROWS][DDIM]
    float *Gs   = Xs + ROWS * DDIM;     // [DDIM] (init staging only)
    float *red  = Gs + DDIM;            // [32]
    float *aux  = red + 32;             // [0..15]=xsq [16..31]=dot [32..47]=mu
                                        // [48..63]=lam [64..79]=mu*dot [80..95]=viol
    float *dotp = aux + 96;             // [16 warps][17] padded partial dots
    float4 *Gs4 = (float4 *)Gs;
    __shared__ unsigned s_base;

    const int tid  = threadIdx.x;
    const int blk  = blockIdx.x;
    const int lane = tid & 31;
    const int w    = tid >> 5;
    const int ds   = blk * DSL;
    float *gbank[3] = { (blk & 1) ? g_gB[0] : g_gA[0],
                        (blk & 1) ? g_gB[1] : g_gA[1],
                        (blk & 1) ? g_gB[2] : g_gA[2] };

    if (tid == 0) s_base = ld_rlx(&g_cnt);   // baseline, far before first arrive
    unsigned cnt = 0;

    // ---- load tokens: X[k,:] = mean_b in[k,b,:]; xsq per row ----
    const float inv_b = 1.0f / (float)NBATCH;
    {
        const int r = w;                 // one row per warp
        const int k = blk * ROWS + r;
        const float4 *src = (const float4 *)(in + (size_t)k * NBATCH * DDIM);
        float4 *dst = (float4 *)(Xs + r * DDIM);
        float ss = 0.0f;
        for (int j = 0; j < 16; j += 2) {        // 32 LDG.128 in flight
            const int dA = lane + j * 32;
            const int dB = dA + 32;
            float4 a = make_float4(0.f, 0.f, 0.f, 0.f);
            float4 c = make_float4(0.f, 0.f, 0.f, 0.f);
#pragma unroll
            for (int b = 0; b < NBATCH; b++) {
                float4 t = src[b * D4 + dA];
                float4 u = src[b * D4 + dB];
                a.x += t.x; a.y += t.y; a.z += t.z; a.w += t.w;
                c.x += u.x; c.y += u.y; c.z += u.z; c.w += u.w;
            }
            a.x *= inv_b; a.y *= inv_b; a.z *= inv_b; a.w *= inv_b;
            c.x *= inv_b; c.y *= inv_b; c.z *= inv_b; c.w *= inv_b;
            dst[dA] = a; dst[dB] = c;
            ss += a.x * a.x + a.y * a.y + a.z * a.z + a.w * a.w;
            ss += c.x * c.x + c.y * c.y + c.z * c.z + c.w * c.w;
        }
#pragma unroll
        for (int o = 16; o > 0; o >>= 1) ss += __shfl_down_sync(0xffffffffu, ss, o);
        if (lane == 0) aux[r] = ss;
    }
    __syncthreads();

    // w0_k = log_map0 scale / K (stored temporarily in aux[16..31])
    if (tid < ROWS) {
        const float xs = aux[tid];
        const float n  = sqrtf(xs);
        const float s  = fminf(n, 1.0f - EPSF);
        const float sc = (n < EPSF) ? 0.0f : atanhf(s) / (n + EPSF);
        aux[16 + tid] = sc * (1.0f / (float)KTOK);
    }
    __syncthreads();

    // ---- m partial straight after own load (g_m pre-zeroed by invariant) --
    {
        const float4 *Xs4 = (const float4 *)Xs;
        float4 acc = make_float4(0.f, 0.f, 0.f, 0.f);
#pragma unroll
        for (int r = 0; r < ROWS; r++) {
            const float wr = aux[16 + r];
            float4 x = Xs4[r * D4 + tid];
            acc.x += wr * x.x; acc.y += wr * x.y;
            acc.z += wr * x.z; acc.w += wr * x.w;
        }
        atomicAdd((float4 *)&g_m[4 * tid], acc);
    }

    const unsigned base = s_base;
    grid_bar(base + (++cnt) * NBLK);   // m complete

    // ---- p0 = exp_map0(m): scalars + initial dots (p never materialized) ----
    float p_sq;
    {
        const float4 mv = __ldcg((const float4 *)&g_m[4 * tid]);
        Gs4[tid] = mv;
        float part = mv.x * mv.x + mv.y * mv.y + mv.z * mv.z + mv.w * mv.w;
        __syncthreads();               // Gs = m visible
        const float msq = block_sum(part, red);
        const float n   = sqrtf(msq);
        const float sc  = (n < EPSF) ? 0.0f : tanhf(n) / (n + EPSF);
        p_sq = sc * sc * msq;
        const float xm = row_dot((const float4 *)(Xs + w * DDIM), Gs4, lane);
        if (lane == 0) aux[16 + w] = sc * xm;   // dot_r = x_r . p0
        __syncthreads();
    }

    // ========= Karcher loop: ONE barrier per iteration =========
    for (int it = 0; it < MAXIT; it++) {
        const int b  = it % 3;
        const int nx = (it + 1) % 3;

        // lam/mu from current dot (warp-local scalars)
        if (lane == 0) {
            float lam, mu;
            const float d0 = aux[16 + w];
            lam_mu(d0, aux[w], p_sq, lam, mu);
            aux[32 + w] = mu;
            aux[48 + w] = lam;
            aux[64 + w] = mu * d0;     // contribution to pG = p.G
        }
        __syncthreads();               // mu + partials visible

        if (tid == 0) {
            float sl = 0.0f, pp = 0.0f;
#pragma unroll
            for (int i = 0; i < NWARP; i++) { sl += aux[48 + i]; pp += aux[64 + i]; }
            atomicAdd(&g_sc[b], make_float4(sl, pp, 0.f, 0.f));
        }

        // G partial into own bank of buffer b (64 atomics per address)
        {
            const float4 *Xs4 = (const float4 *)Xs;
            float4 acc = make_float4(0.f, 0.f, 0.f, 0.f);
#pragma unroll
            for (int r = 0; r < ROWS; r++) {
                const float mr = aux[32 + r];
                float4 x = Xs4[r * D4 + tid];
                acc.x += mr * x.x; acc.y += mr * x.y;
                acc.z += mr * x.z; acc.w += mr * x.w;
            }
            atomicAdd((float4 *)&gbank[b][4 * tid], acc);
        }

        // zero buffer nx (both banks, own slice) for iteration it+1
        if (tid < DSL) {
            g_gA[nx][ds + tid] = 0.0f;
            g_gB[nx][ds + tid] = 0.0f;
        }
        if (blk == 0 && tid == 0) g_sc[nx] = make_float4(0.f, 0.f, 0.f, 0.f);

        grid_bar(base + (++cnt) * NBLK);   // G[b] + scalars complete chip-wide

        // read G = A + B (register-resident; no SMEM staging)
        const float4 scl = __ldcg(&g_sc[b]);
        const float4 Ga  = __ldcg((const float4 *)&g_gA[b][4 * tid]);
        const float4 Gb  = __ldcg((const float4 *)&g_gB[b][4 * tid]);
        float4 Gv;
        Gv.x = Ga.x + Gb.x; Gv.y = Ga.y + Gb.y;
        Gv.z = Ga.z + Gb.z; Gv.w = Ga.w + Gb.w;
        float ggp = Gv.x * Gv.x + Gv.y * Gv.y + Gv.z * Gv.z + Gv.w * Gv.w;

        // column-sliced dots: thread tid owns d4=tid; 2 chunks of 8 rows
        {
            const float4 *Xs4 = (const float4 *)Xs;
#pragma unroll
            for (int r0 = 0; r0 < ROWS; r0 += 8) {
                float pr[8];
#pragma unroll
                for (int q = 0; q < 8; q++) {
                    float4 x = Xs4[(r0 + q) * D4 + tid];
                    pr[q] = x.x * Gv.x + x.y * Gv.y + x.z * Gv.z + x.w * Gv.w;
                }
#pragma unroll
                for (int q = 0; q < 8; q++) {
                    float v = pr[q];
#pragma unroll
                    for (int o = 16; o > 0; o >>= 1)
                        v += __shfl_down_sync(0xffffffffu, v, o);
                    if (lane == 0) dotp[w * 17 + r0 + q] = v;
                }
            }
        }

        // GG block_sum (its first syncthreads also publishes dotp)
        const float GG = block_sum(ggp, red);

        // cross-warp reduce: warp w produces xG for its row w
        float xG;
        {
            float v = (lane < NWARP) ? dotp[lane * 17 + w] : 0.0f;
#pragma unroll
            for (int o = 8; o > 0; o >>= 1)
                v += __shfl_down_sync(0xffffffffu, v, o);
            xG = v;   // valid on lane 0
        }

        // scalar update: p_{t+1} = alpha*p + beta*G  (grad = G - slam*p)
        const float slam = scl.x;
        const float pG   = scl.y;
        const float gg   = fmaxf(GG - 2.0f * slam * pG + slam * slam * p_sq, 0.0f);
        const float pg   = pG - slam * p_sq;
        float alpha = 1.0f, beta = 0.0f, cf = 1.0f, p_new = p_sq;
        const float n_v = STEPSZ * sqrtf(gg);
        if (n_v >= EPSF) {
            const float sc  = tanhf(0.5f * n_v) / (n_v + EPSF);
            const float xy  = -STEPSZ * sc * pg;
            const float ysq = STEPSZ * STEPSZ * sc * sc * gg;
            const float xsc = fminf(p_sq, 0.99f);
            const float ysc = fminf(ysq, 0.99f);
            const float A   = 1.0f + 2.0f * xy + ysc;
            const float B   = 1.0f - xsc;
            const float dn  = fmaxf(1.0f + 2.0f * xy + xsc * ysc, EPSF);
            const float cbg = (-STEPSZ * sc) * B / dn;   // coeff on grad
            alpha = A / dn - cbg * slam;                 // coeff on p
            beta  = cbg;                                 // coeff on G
            p_new = alpha * alpha * p_sq + 2.0f * alpha * beta * pG
                  + beta * beta * GG;
            const float rn = sqrtf(p_new);
            if (rn >= 1.0f - EPSF) {
                cf = (1.0f - 2.0f * EPSF) / rn;
                p_new *= cf * cf;
            }
        }
        p_sq = p_new;
        if (lane == 0)
            aux[16 + w] = cf * (alpha * aux[16 + w] + beta * xG);
        // next iteration's post-lam_mu sync orders the aux writes
    }

    // ---- final distances + violation (1 RED per CTA) ----
    if (lane == 0) {
        const float xs  = aux[w];
        const float dot = aux[16 + w];
        const float dsq = xs - 2.0f * dot + p_sq;
        const float den = fmaxf((1.0f - xs) * (1.0f - p_sq), EPSF);
        const float fr  = fmaxf(dsq / den, 0.0f);
        const float dd  = asinhf(sqrtf(fr));
        aux[80 + w] = fmaxf(dd - 2.0f, 0.0f);
    }
    __syncthreads();
    if (tid == 0) {
        float vi = 0.0f;
#pragma unroll
        for (int i = 0; i < NWARP; i++) vi += aux[80 + i];
        atomicAdd(&g_viol, vi);
    }
    __syncthreads();

    // ---- last-arriver writes output (no final grid barrier) ----
    if (tid == 0) {
        __threadfence();               // make own viol RED visible first
        const unsigned old = atomicAdd(&g_cnt, 1u);
        if (old == base + cnt * NBLK + (NBLK - 1u)) {
            __threadfence();           // acquire: all CTAs' viol REDs done
            out[0] = __ldcg(&g_viol) * (1.0f / (float)KTOK);
            g_viol = 0.0f;
            g_sc[0] = make_float4(0.f, 0.f, 0.f, 0.f);
            g_sc[1] = make_float4(0.f, 0.f, 0.f, 0.f);
        }
    }

    // ---- restore zeroed-on-exit invariant (dirty: g_m, banks 0 and 1) ----
    if (tid < DSL) {
        g_m[ds + tid] = 0.0f;
        g_gA[0][ds + tid] = 0.0f;
        g_gA[1][ds + tid] = 0.0f;
        g_gB[0][ds + tid] = 0.0f;
        g_gB[1][ds + tid] = 0.0f;
    }
}

extern "C" void kernel_launch(void* const* d_in, const int* in_sizes, int n_in,
                              void* d_out, int out_size)
{
    (void)in_sizes; (void)n_in; (void)out_size;
    cudaFuncSetAttribute(traj_kernel,
                         cudaFuncAttributeMaxDynamicSharedMemorySize, SMEM_BYTES);
    const float *in = (const float *)d_in[0];
    float *out = (float *)d_out;
    traj_kernel<<<NBLK, NTHR, SMEM_BYTES>>>(in, out);
}

// round 16
// speedup vs baseline: 1.0153x; 1.0153x over previous
#include <cuda_runtime.h>
#include <math.h>

#define KTOK 2048
#define DDIM 2048
#define NBATCH 16
#define MAXIT 50
#define EPSF 1e-8f
#define STEPSZ (0.1f / 2048.0f)

#define NBLK 128
#define NTHR 512
#define NWARP 16
#define ROWS 16                 // tokens per CTA, one row per warp
#define DSL (DDIM / NBLK)       // 16 d-elements per CTA slice
#define D4  (DDIM / 4)          // 512 float4
#define NBANK 4

// smem: Xs[ROWS*DDIM] + Gs[DDIM] + red[32] + aux[96] + dotp[16*17]
#define SMEM_FLOATS (ROWS * DDIM + DDIM + 32 + 96 + 272)
#define SMEM_BYTES (SMEM_FLOATS * 4)

// ------------- global scratch (ZEROED-ON-EXIT invariant) ------------------
__device__ __align__(16) float g_m[DDIM];
__device__ __align__(16) float g_g[NBANK][3][DDIM];  // banked triple buffer
__device__ __align__(16) float4 g_sc[3];             // (slam, pG, 0, 0)
__device__ float g_viol;
__device__ unsigned g_cnt;          // monotonic barrier counter

__device__ __forceinline__ unsigned ld_rlx(const unsigned *p)
{
    unsigned v;
    asm volatile("ld.relaxed.gpu.b32 %0, [%1];" : "=r"(v) : "l"(p) : "memory");
    return v;
}

// ------------- counter grid barrier: 1 RED arrive + 1 poller per CTA -----
__device__ __forceinline__ void grid_bar(unsigned target)
{
    __syncthreads();
    if (threadIdx.x == 0) {
        __threadfence();                  // release
        atomicAdd(&g_cnt, 1u);
        while (ld_rlx(&g_cnt) < target) {}
        __threadfence();                  // acquire
    }
    __syncthreads();
}

// deterministic block-wide sum: identical value on every thread & every CTA
__device__ __forceinline__ float block_sum(float v, float *red)
{
#pragma unroll
    for (int o = 16; o > 0; o >>= 1) v += __shfl_down_sync(0xffffffffu, v, o);
    __syncthreads();
    if ((threadIdx.x & 31) == 0) red[threadIdx.x >> 5] = v;
    __syncthreads();
    float s = red[0];
#pragma unroll
    for (int i = 1; i < NWARP; i++) s += red[i];
    __syncthreads();
    return s;
}

// ---- fast transcendentals (MUFU-based); values here are O(0.1), margins huge
__device__ __forceinline__ float fast_atanh(float s)
{
    return 0.5f * __logf(__fdividef(1.0f + s, 1.0f - s));
}
__device__ __forceinline__ float fast_tanh(float x)
{
    const float e = __expf(2.0f * x);
    return __fdividef(e - 1.0f, e + 1.0f);
}

// log_map_at coefficients: v_k = -lam*p + mu*x_k, scalars only.
__device__ __forceinline__ void lam_mu(float dot, float xs, float p_sq,
                                       float &lam, float &mu)
{
    const float xy  = -dot;
    const float xsc = fminf(p_sq, 0.99f);
    const float ysc = fminf(xs, 0.99f);
    const float a   = 1.0f + 2.0f * xy + ysc;
    const float b   = 1.0f - xsc;
    const float den = fmaxf(1.0f + 2.0f * xy + xsc * ysc, EPSF);
    const float numsq = fmaxf(a * a * p_sq + b * b * xs - 2.0f * a * b * dot, 0.0f);
    const float rn  = __fdividef(sqrtf(numsq), den);
    const float maxn = 1.0f - EPSF;
    const float c   = (rn >= maxn) ? __fdividef(maxn - EPSF, rn) : 1.0f;
    const float n   = rn * c;
    const float s   = fminf(n, 1.0f - EPSF);
    const float scale = 2.0f * __fdividef(fast_atanh(s), n + EPSF);
    const float t   = (n < EPSF) ? 0.0f : __fdividef(scale * c, den);
    lam = t * a;
    mu  = t * b;
}

// float4 row-dot over SMEM (init phase only)
__device__ __forceinline__ float row_dot(const float4 *xr4, const float4 *vv4,
                                         int lane)
{
    float acc0 = 0.0f, acc1 = 0.0f;
#pragma unroll 4
    for (int j = 0; j < 16; j++) {
        const int d4 = lane + j * 32;
        float4 x = xr4[d4];
        float4 p = vv4[d4];
        acc0 += x.x * p.x + x.y * p.y;
        acc1 += x.z * p.z + x.w * p.w;
    }
    float p2 = acc0 + acc1;
#pragma unroll
    for (int o = 16; o > 0; o >>= 1) p2 += __shfl_down_sync(0xffffffffu, p2, o);
    return p2;   // valid on lane 0
}

__global__ void __launch_bounds__(NTHR, 1)
traj_kernel(const float *__restrict__ in, float *__restrict__ out)
{
    extern __shared__ float smem[];
    float *Xs   = smem;                 // [ROWS][DDIM]
    float *Gs   = Xs + ROWS * DDIM;     // [DDIM] (init staging only)
    float *red  = Gs + DDIM;            // [32]
    float *aux  = red + 32;             // [0..15]=xsq [16..31]=dot [32..47]=mu
                                        // [48..63]=lam [64..79]=mu*dot [80..95]=viol
    float *dotp = aux + 96;             // [16 warps][17] padded partial dots
    float4 *Gs4 = (float4 *)Gs;
    __shared__ unsigned s_base;

    const int tid  = threadIdx.x;
    const int blk  = blockIdx.x;
    const int lane = tid & 31;
    const int w    = tid >> 5;
    const int ds   = blk * DSL;
    const int mybk = blk & (NBANK - 1);

    if (tid == 0) s_base = ld_rlx(&g_cnt);   // baseline, far before first arrive
    unsigned cnt = 0;

    // ---- load tokens: X[k,:] = mean_b in[k,b,:]; xsq per row ----
    const float inv_b = 1.0f / (float)NBATCH;
    {
        const int r = w;                 // one row per warp
        const int k = blk * ROWS + r;
        const float4 *src = (const float4 *)(in + (size_t)k * NBATCH * DDIM);
        float4 *dst = (float4 *)(Xs + r * DDIM);
        float ss = 0.0f;
        for (int j = 0; j < 16; j += 2) {        // 32 LDG.128 in flight
            const int dA = lane + j * 32;
            const int dB = dA + 32;
            float4 a = make_float4(0.f, 0.f, 0.f, 0.f);
            float4 c = make_float4(0.f, 0.f, 0.f, 0.f);
#pragma unroll
            for (int b = 0; b < NBATCH; b++) {
                float4 t = src[b * D4 + dA];
                float4 u = src[b * D4 + dB];
                a.x += t.x; a.y += t.y; a.z += t.z; a.w += t.w;
                c.x += u.x; c.y += u.y; c.z += u.z; c.w += u.w;
            }
            a.x *= inv_b; a.y *= inv_b; a.z *= inv_b; a.w *= inv_b;
            c.x *= inv_b; c.y *= inv_b; c.z *= inv_b; c.w *= inv_b;
            dst[dA] = a; dst[dB] = c;
            ss += a.x * a.x + a.y * a.y + a.z * a.z + a.w * a.w;
            ss += c.x * c.x + c.y * c.y + c.z * c.z + c.w * c.w;
        }
#pragma unroll
        for (int o = 16; o > 0; o >>= 1) ss += __shfl_down_sync(0xffffffffu, ss, o);
        if (lane == 0) aux[r] = ss;
    }
    __syncthreads();

    // w0_k = log_map0 scale / K (stored temporarily in aux[16..31])
    if (tid < ROWS) {
        const float xs = aux[tid];
        const float n  = sqrtf(xs);
        const float s  = fminf(n, 1.0f - EPSF);
        const float sc = (n < EPSF) ? 0.0f : __fdividef(fast_atanh(s), n + EPSF);
        aux[16 + tid] = sc * (1.0f / (float)KTOK);
    }
    __syncthreads();

    // ---- m partial straight after own load (g_m pre-zeroed by invariant) --
    {
        const float4 *Xs4 = (const float4 *)Xs;
        float4 acc = make_float4(0.f, 0.f, 0.f, 0.f);
#pragma unroll
        for (int r = 0; r < ROWS; r++) {
            const float wr = aux[16 + r];
            float4 x = Xs4[r * D4 + tid];
            acc.x += wr * x.x; acc.y += wr * x.y;
            acc.z += wr * x.z; acc.w += wr * x.w;
        }
        atomicAdd((float4 *)&g_m[4 * tid], acc);
    }

    const unsigned base = s_base;
    grid_bar(base + (++cnt) * NBLK);   // m complete

    // ---- p0 = exp_map0(m): scalars + initial dots (p never materialized) ----
    float p_sq;
    {
        const float4 mv = __ldcg((const float4 *)&g_m[4 * tid]);
        Gs4[tid] = mv;
        float part = mv.x * mv.x + mv.y * mv.y + mv.z * mv.z + mv.w * mv.w;
        __syncthreads();               // Gs = m visible
        const float msq = block_sum(part, red);
        const float n   = sqrtf(msq);
        const float sc  = (n < EPSF) ? 0.0f : __fdividef(fast_tanh(n), n + EPSF);
        p_sq = sc * sc * msq;
        const float xm = row_dot((const float4 *)(Xs + w * DDIM), Gs4, lane);
        if (lane == 0) aux[16 + w] = sc * xm;   // dot_r = x_r . p0
        __syncthreads();
    }

    // ========= Karcher loop: ONE barrier per iteration =========
    for (int it = 0; it < MAXIT; it++) {
        const int b  = it % 3;
        const int nx = (it + 1) % 3;

        // lam/mu from current dot (warp-local scalars)
        if (lane == 0) {
            float lam, mu;
            const float d0 = aux[16 + w];
            lam_mu(d0, aux[w], p_sq, lam, mu);
            aux[32 + w] = mu;
            aux[48 + w] = lam;
            aux[64 + w] = mu * d0;     // contribution to pG = p.G
        }
        __syncthreads();               // mu + partials visible

        if (tid == 0) {
            float sl = 0.0f, pp = 0.0f;
#pragma unroll
            for (int i = 0; i < NWARP; i++) { sl += aux[48 + i]; pp += aux[64 + i]; }
            atomicAdd(&g_sc[b], make_float4(sl, pp, 0.f, 0.f));
        }

        // G partial into own bank of buffer b (32 atomics per address)
        {
            const float4 *Xs4 = (const float4 *)Xs;
            float4 acc = make_float4(0.f, 0.f, 0.f, 0.f);
#pragma unroll
            for (int r = 0; r < ROWS; r++) {
                const float mr = aux[32 + r];
                float4 x = Xs4[r * D4 + tid];
                acc.x += mr * x.x; acc.y += mr * x.y;
                acc.z += mr * x.z; acc.w += mr * x.w;
            }
            atomicAdd((float4 *)&g_g[mybk][b][4 * tid], acc);
        }

        // zero buffer nx (all banks, own slice) for iteration it+1
        if (tid < NBANK * DSL)
            g_g[tid / DSL][nx][ds + (tid & (DSL - 1))] = 0.0f;
        if (blk == 0 && tid == 0) g_sc[nx] = make_float4(0.f, 0.f, 0.f, 0.f);

        grid_bar(base + (++cnt) * NBLK);   // G[b] + scalars complete chip-wide

        // read G = sum of banks (register-resident)
        const float4 scl = __ldcg(&g_sc[b]);
        float4 Gv = make_float4(0.f, 0.f, 0.f, 0.f);
#pragma unroll
        for (int bk = 0; bk < NBANK; bk++) {
            const float4 t = __ldcg((const float4 *)&g_g[bk][b][4 * tid]);
            Gv.x += t.x; Gv.y += t.y; Gv.z += t.z; Gv.w += t.w;
        }
        float ggp = Gv.x * Gv.x + Gv.y * Gv.y + Gv.z * Gv.z + Gv.w * Gv.w;

        // column-sliced dots: thread tid owns d4=tid; 2 chunks of 8 rows
        {
            const float4 *Xs4 = (const float4 *)Xs;
#pragma unroll
            for (int r0 = 0; r0 < ROWS; r0 += 8) {
                float pr[8];
#pragma unroll
                for (int q = 0; q < 8; q++) {
                    float4 x = Xs4[(r0 + q) * D4 + tid];
                    pr[q] = x.x * Gv.x + x.y * Gv.y + x.z * Gv.z + x.w * Gv.w;
                }
#pragma unroll
                for (int q = 0; q < 8; q++) {
                    float v = pr[q];
#pragma unroll
                    for (int o = 16; o > 0; o >>= 1)
                        v += __shfl_down_sync(0xffffffffu, v, o);
                    if (lane == 0) dotp[w * 17 + r0 + q] = v;
                }
            }
        }

        // GG block_sum (its first syncthreads also publishes dotp)
        const float GG = block_sum(ggp, red);

        // cross-warp reduce: warp w produces xG for its row w
        float xG;
        {
            float v = (lane < NWARP) ? dotp[lane * 17 + w] : 0.0f;
#pragma unroll
            for (int o = 8; o > 0; o >>= 1)
                v += __shfl_down_sync(0xffffffffu, v, o);
            xG = v;   // valid on lane 0
        }

        // scalar update: p_{t+1} = alpha*p + beta*G  (grad = G - slam*p)
        const float slam = scl.x;
        const float pG   = scl.y;
        const float gg   = fmaxf(GG - 2.0f * slam * pG + slam * slam * p_sq, 0.0f);
        const float pg   = pG - slam * p_sq;
        float alpha = 1.0f, beta = 0.0f, cf = 1.0f, p_new = p_sq;
        const float n_v = STEPSZ * sqrtf(gg);
        if (n_v >= EPSF) {
            const float sc  = __fdividef(fast_tanh(0.5f * n_v), n_v + EPSF);
            const float xy  = -STEPSZ * sc * pg;
            const float ysq = STEPSZ * STEPSZ * sc * sc * gg;
            const float xsc = fminf(p_sq, 0.99f);
            const float ysc = fminf(ysq, 0.99f);
            const float A   = 1.0f + 2.0f * xy + ysc;
            const float B   = 1.0f - xsc;
            const float dn  = fmaxf(1.0f + 2.0f * xy + xsc * ysc, EPSF);
            const float cbg = (-STEPSZ * sc) * __fdividef(B, dn);  // coeff on grad
            alpha = __fdividef(A, dn) - cbg * slam;                // coeff on p
            beta  = cbg;                                           // coeff on G
            p_new = alpha * alpha * p_sq + 2.0f * alpha * beta * pG
                  + beta * beta * GG;
            const float rn = sqrtf(p_new);
            if (rn >= 1.0f - EPSF) {
                cf = __fdividef(1.0f - 2.0f * EPSF, rn);
                p_new *= cf * cf;
            }
        }
        p_sq = p_new;
        if (lane == 0)
            aux[16 + w] = cf * (alpha * aux[16 + w] + beta * xG);
        // next iteration's post-lam_mu sync orders the aux writes
    }

    // ---- final distances + violation (1 RED per CTA) ----
    if (lane == 0) {
        const float xs  = aux[w];
        const float dot = aux[16 + w];
        const float dsq = xs - 2.0f * dot + p_sq;
        const float den = fmaxf((1.0f - xs) * (1.0f - p_sq), EPSF);
        const float fr  = fmaxf(__fdividef(dsq, den), 0.0f);
        const float dd  = asinhf(sqrtf(fr));
        aux[80 + w] = fmaxf(dd - 2.0f, 0.0f);
    }
    __syncthreads();
    if (tid == 0) {
        float vi = 0.0f;
#pragma unroll
        for (int i = 0; i < NWARP; i++) vi += aux[80 + i];
        atomicAdd(&g_viol, vi);
    }
    __syncthreads();

    // ---- last-arriver writes output (no final grid barrier) ----
    if (tid == 0) {
        __threadfence();               // make own viol RED visible first
        const unsigned old = atomicAdd(&g_cnt, 1u);
        if (old == base + cnt * NBLK + (NBLK - 1u)) {
            __threadfence();           // acquire: all CTAs' viol REDs done
            out[0] = __ldcg(&g_viol) * (1.0f / (float)KTOK);
            g_viol = 0.0f;
            g_sc[0] = make_float4(0.f, 0.f, 0.f, 0.f);
            g_sc[1] = make_float4(0.f, 0.f, 0.f, 0.f);
        }
    }

    // ---- restore zeroed-on-exit invariant (dirty: g_m, banks buf 0 and 1) --
    if (tid < DSL) g_m[ds + tid] = 0.0f;
    if (tid < NBANK * DSL) {
        const int bk = tid / DSL;
        const int e  = ds + (tid & (DSL - 1));
        g_g[bk][0][e] = 0.0f;
        g_g[bk][1][e] = 0.0f;
    }
}

extern "C" void kernel_launch(void* const* d_in, const int* in_sizes, int n_in,
                              void* d_out, int out_size)
{
    (void)in_sizes; (void)n_in; (void)out_size;
    cudaFuncSetAttribute(traj_kernel,
                         cudaFuncAttributeMaxDynamicSharedMemorySize, SMEM_BYTES);
    const float *in = (const float *)d_in[0];
    float *out = (float *)d_out;
    traj_kernel<<<NBLK, NTHR, SMEM_BYTES>>>(in, out);
}

// round 17
// speedup vs baseline: 1.0754x; 1.0592x over previous
#include <cuda_runtime.h>
#include <math.h>

#define KTOK 2048
#define DDIM 2048
#define NBATCH 16
#define MAXIT 50
#define EPSF 1e-8f
#define STEPSZ (0.1f / 2048.0f)

#define NBLK 128
#define NTHR 512
#define NWARP 16
#define ROWS 16                 // tokens per CTA, one row per warp
#define DSL (DDIM / NBLK)       // 16 d-elements per CTA slice
#define D4  (DDIM / 4)          // 512 float4
#define NBANK 4

// smem: Xs[ROWS*DDIM] + Gs[DDIM] + red[32] + aux[96] + dotp[16*17]
#define SMEM_FLOATS (ROWS * DDIM + DDIM + 32 + 96 + 272)
#define SMEM_BYTES (SMEM_FLOATS * 4)

// ------------- global scratch (ZEROED-ON-EXIT invariant) ------------------
__device__ __align__(16) float g_m[DDIM];
__device__ __align__(16) float g_g[NBANK][3][DDIM];  // banked triple buffer
__device__ __align__(16) float4 g_sc[3];             // (slam, pG, 0, 0)
__device__ float g_viol;
__device__ unsigned g_cnt;          // monotonic barrier counter

__device__ __forceinline__ unsigned ld_rlx(const unsigned *p)
{
    unsigned v;
    asm volatile("ld.relaxed.gpu.b32 %0, [%1];" : "=r"(v) : "l"(p) : "memory");
    return v;
}
__device__ __forceinline__ unsigned ld_acq(const unsigned *p)
{
    unsigned v;
    asm volatile("ld.acquire.gpu.b32 %0, [%1];" : "=r"(v) : "l"(p) : "memory");
    return v;
}
__device__ __forceinline__ void red_release_add(unsigned *p, unsigned v)
{
    asm volatile("red.release.gpu.global.add.u32 [%0], %1;"
                 :: "l"(p), "r"(v) : "memory");
}

// ---- counter grid barrier: release-RED arrive + relaxed poll + acquire ----
__device__ __forceinline__ void grid_bar(unsigned target)
{
    __syncthreads();                       // block writes ordered before arrive
    if (threadIdx.x == 0) {
        red_release_add(&g_cnt, 1u);       // fused release (no MEMBAR stall)
        while (ld_rlx(&g_cnt) < target) {}
        (void)ld_acq(&g_cnt);              // acquire: order subsequent reads
    }
    __syncthreads();
}

// deterministic block-wide sum: identical value on every thread & every CTA
__device__ __forceinline__ float block_sum(float v, float *red)
{
#pragma unroll
    for (int o = 16; o > 0; o >>= 1) v += __shfl_down_sync(0xffffffffu, v, o);
    __syncthreads();
    if ((threadIdx.x & 31) == 0) red[threadIdx.x >> 5] = v;
    __syncthreads();
    float s = red[0];
#pragma unroll
    for (int i = 1; i < NWARP; i++) s += red[i];
    __syncthreads();
    return s;
}

// ---- fast transcendentals (MUFU-based); values here are O(0.1), margins huge
__device__ __forceinline__ float fast_atanh(float s)
{
    return 0.5f * __logf(__fdividef(1.0f + s, 1.0f - s));
}
__device__ __forceinline__ float fast_tanh(float x)
{
    const float e = __expf(2.0f * x);
    return __fdividef(e - 1.0f, e + 1.0f);
}

// log_map_at coefficients: v_k = -lam*p + mu*x_k, scalars only.
__device__ __forceinline__ void lam_mu(float dot, float xs, float p_sq,
                                       float &lam, float &mu)
{
    const float xy  = -dot;
    const float xsc = fminf(p_sq, 0.99f);
    const float ysc = fminf(xs, 0.99f);
    const float a   = 1.0f + 2.0f * xy + ysc;
    const float b   = 1.0f - xsc;
    const float den = fmaxf(1.0f + 2.0f * xy + xsc * ysc, EPSF);
    const float numsq = fmaxf(a * a * p_sq + b * b * xs - 2.0f * a * b * dot, 0.0f);
    const float rn  = __fdividef(sqrtf(numsq), den);
    const float maxn = 1.0f - EPSF;
    const float c   = (rn >= maxn) ? __fdividef(maxn - EPSF, rn) : 1.0f;
    const float n   = rn * c;
    const float s   = fminf(n, 1.0f - EPSF);
    const float scale = 2.0f * __fdividef(fast_atanh(s), n + EPSF);
    const float t   = (n < EPSF) ? 0.0f : __fdividef(scale * c, den);
    lam = t * a;
    mu  = t * b;
}

// float4 row-dot over SMEM (init phase only)
__device__ __forceinline__ float row_dot(const float4 *xr4, const float4 *vv4,
                                         int lane)
{
    float acc0 = 0.0f, acc1 = 0.0f;
#pragma unroll 4
    for (int j = 0; j < 16; j++) {
        const int d4 = lane + j * 32;
        float4 x = xr4[d4];
        float4 p = vv4[d4];
        acc0 += x.x * p.x + x.y * p.y;
        acc1 += x.z * p.z + x.w * p.w;
    }
    float p2 = acc0 + acc1;
#pragma unroll
    for (int o = 16; o > 0; o >>= 1) p2 += __shfl_down_sync(0xffffffffu, p2, o);
    return p2;   // valid on lane 0
}

__global__ void __launch_bounds__(NTHR, 1)
traj_kernel(const float *__restrict__ in, float *__restrict__ out)
{
    extern __shared__ float smem[];
    float *Xs   = smem;                 // [ROWS][DDIM]
    float *Gs   = Xs + ROWS * DDIM;     // [DDIM] (init staging only)
    float *red  = Gs + DDIM;            // [32]
    float *aux  = red + 32;             // [0..15]=xsq [16..31]=dot [32..47]=mu
                                        // [48..63]=lam [64..79]=mu*dot [80..95]=viol
    float *dotp = aux + 96;             // [16 warps][17] padded partial dots
    float4 *Gs4 = (float4 *)Gs;
    __shared__ unsigned s_base;

    const int tid  = threadIdx.x;
    const int blk  = blockIdx.x;
    const int lane = tid & 31;
    const int w    = tid >> 5;
    const int ds   = blk * DSL;
    const int mybk = blk & (NBANK - 1);

    if (tid == 0) s_base = ld_rlx(&g_cnt);   // baseline, far before first arrive
    unsigned cnt = 0;

    // ---- load tokens: X[k,:] = mean_b in[k,b,:]; xsq per row ----
    const float inv_b = 1.0f / (float)NBATCH;
    {
        const int r = w;                 // one row per warp
        const int k = blk * ROWS + r;
        const float4 *src = (const float4 *)(in + (size_t)k * NBATCH * DDIM);
        float4 *dst = (float4 *)(Xs + r * DDIM);
        float ss = 0.0f;
        for (int j = 0; j < 16; j += 2) {        // 32 LDG.128 in flight
            const int dA = lane + j * 32;
            const int dB = dA + 32;
            float4 a = make_float4(0.f, 0.f, 0.f, 0.f);
            float4 c = make_float4(0.f, 0.f, 0.f, 0.f);
#pragma unroll
            for (int b = 0; b < NBATCH; b++) {
                float4 t = src[b * D4 + dA];
                float4 u = src[b * D4 + dB];
                a.x += t.x; a.y += t.y; a.z += t.z; a.w += t.w;
                c.x += u.x; c.y += u.y; c.z += u.z; c.w += u.w;
            }
            a.x *= inv_b; a.y *= inv_b; a.z *= inv_b; a.w *= inv_b;
            c.x *= inv_b; c.y *= inv_b; c.z *= inv_b; c.w *= inv_b;
            dst[dA] = a; dst[dB] = c;
            ss += a.x * a.x + a.y * a.y + a.z * a.z + a.w * a.w;
            ss += c.x * c.x + c.y * c.y + c.z * c.z + c.w * c.w;
        }
#pragma unroll
        for (int o = 16; o > 0; o >>= 1) ss += __shfl_down_sync(0xffffffffu, ss, o);
        if (lane == 0) aux[r] = ss;
    }
    __syncthreads();

    // w0_k = log_map0 scale / K (stored temporarily in aux[16..31])
    if (tid < ROWS) {
        const float xs = aux[tid];
        const float n  = sqrtf(xs);
        const float s  = fminf(n, 1.0f - EPSF);
        const float sc = (n < EPSF) ? 0.0f : __fdividef(fast_atanh(s), n + EPSF);
        aux[16 + tid] = sc * (1.0f / (float)KTOK);
    }
    __syncthreads();

    // ---- m partial straight after own load (g_m pre-zeroed by invariant) --
    {
        const float4 *Xs4 = (const float4 *)Xs;
        float4 acc = make_float4(0.f, 0.f, 0.f, 0.f);
#pragma unroll
        for (int r = 0; r < ROWS; r++) {
            const float wr = aux[16 + r];
            float4 x = Xs4[r * D4 + tid];
            acc.x += wr * x.x; acc.y += wr * x.y;
            acc.z += wr * x.z; acc.w += wr * x.w;
        }
        atomicAdd((float4 *)&g_m[4 * tid], acc);
    }

    const unsigned base = s_base;
    grid_bar(base + (++cnt) * NBLK);   // m complete

    // ---- p0 = exp_map0(m): scalars + initial dots (p never materialized) ----
    float p_sq;
    {
        const float4 mv = __ldcg((const float4 *)&g_m[4 * tid]);
        Gs4[tid] = mv;
        float part = mv.x * mv.x + mv.y * mv.y + mv.z * mv.z + mv.w * mv.w;
        __syncthreads();               // Gs = m visible
        const float msq = block_sum(part, red);
        const float n   = sqrtf(msq);
        const float sc  = (n < EPSF) ? 0.0f : __fdividef(fast_tanh(n), n + EPSF);
        p_sq = sc * sc * msq;
        const float xm = row_dot((const float4 *)(Xs + w * DDIM), Gs4, lane);
        if (lane == 0) aux[16 + w] = sc * xm;   // dot_r = x_r . p0
        __syncthreads();
    }

    // ========= Karcher loop: ONE barrier per iteration =========
    for (int it = 0; it < MAXIT; it++) {
        const int b  = it % 3;
        const int nx = (it + 1) % 3;

        // lam/mu from current dot (warp-local scalars)
        if (lane == 0) {
            float lam, mu;
            const float d0 = aux[16 + w];
            lam_mu(d0, aux[w], p_sq, lam, mu);
            aux[32 + w] = mu;
            aux[48 + w] = lam;
            aux[64 + w] = mu * d0;     // contribution to pG = p.G
        }
        __syncthreads();               // mu + partials visible

        if (tid == 0) {
            float sl = 0.0f, pp = 0.0f;
#pragma unroll
            for (int i = 0; i < NWARP; i++) { sl += aux[48 + i]; pp += aux[64 + i]; }
            atomicAdd(&g_sc[b], make_float4(sl, pp, 0.f, 0.f));
        }

        // G partial into own bank of buffer b (32 atomics per address)
        {
            const float4 *Xs4 = (const float4 *)Xs;
            float4 acc = make_float4(0.f, 0.f, 0.f, 0.f);
#pragma unroll
            for (int r = 0; r < ROWS; r++) {
                const float mr = aux[32 + r];
                float4 x = Xs4[r * D4 + tid];
                acc.x += mr * x.x; acc.y += mr * x.y;
                acc.z += mr * x.z; acc.w += mr * x.w;
            }
            atomicAdd((float4 *)&g_g[mybk][b][4 * tid], acc);
        }

        // zero buffer nx (all banks, own slice) for iteration it+1
        // (safe window: all reads of nx finished before barrier it-1)
        if (tid < NBANK * DSL)
            g_g[tid / DSL][nx][ds + (tid & (DSL - 1))] = 0.0f;
        if (blk == 0 && tid == 0) g_sc[nx] = make_float4(0.f, 0.f, 0.f, 0.f);

        grid_bar(base + (++cnt) * NBLK);   // G[b] + scalars complete chip-wide

        // read G = sum of banks (register-resident)
        const float4 scl = __ldcg(&g_sc[b]);
        float4 Gv = make_float4(0.f, 0.f, 0.f, 0.f);
#pragma unroll
        for (int bk = 0; bk < NBANK; bk++) {
            const float4 t = __ldcg((const float4 *)&g_g[bk][b][4 * tid]);
            Gv.x += t.x; Gv.y += t.y; Gv.z += t.z; Gv.w += t.w;
        }
        float ggp = Gv.x * Gv.x + Gv.y * Gv.y + Gv.z * Gv.z + Gv.w * Gv.w;

        // column-sliced dots: thread tid owns d4=tid; 2 chunks of 8 rows
        {
            const float4 *Xs4 = (const float4 *)Xs;
#pragma unroll
            for (int r0 = 0; r0 < ROWS; r0 += 8) {
                float pr[8];
#pragma unroll
                for (int q = 0; q < 8; q++) {
                    float4 x = Xs4[(r0 + q) * D4 + tid];
                    pr[q] = x.x * Gv.x + x.y * Gv.y + x.z * Gv.z + x.w * Gv.w;
                }
#pragma unroll
                for (int q = 0; q < 8; q++) {
                    float v = pr[q];
#pragma unroll
                    for (int o = 16; o > 0; o >>= 1)
                        v += __shfl_down_sync(0xffffffffu, v, o);
                    if (lane == 0) dotp[w * 17 + r0 + q] = v;
                }
            }
        }

        // GG block_sum (its first syncthreads also publishes dotp)
        const float GG = block_sum(ggp, red);

        // cross-warp reduce: warp w produces xG for its row w
        float xG;
        {
            float v = (lane < NWARP) ? dotp[lane * 17 + w] : 0.0f;
#pragma unroll
            for (int o = 8; o > 0; o >>= 1)
                v += __shfl_down_sync(0xffffffffu, v, o);
            xG = v;   // valid on lane 0
        }

        // scalar update: p_{t+1} = alpha*p + beta*G  (grad = G - slam*p)
        const float slam = scl.x;
        const float pG   = scl.y;
        const float gg   = fmaxf(GG - 2.0f * slam * pG + slam * slam * p_sq, 0.0f);
        const float pg   = pG - slam * p_sq;
        float alpha = 1.0f, beta = 0.0f, cf = 1.0f, p_new = p_sq;
        const float n_v = STEPSZ * sqrtf(gg);
        if (n_v >= EPSF) {
            const float sc  = __fdividef(fast_tanh(0.5f * n_v), n_v + EPSF);
            const float xy  = -STEPSZ * sc * pg;
            const float ysq = STEPSZ * STEPSZ * sc * sc * gg;
            const float xsc = fminf(p_sq, 0.99f);
            const float ysc = fminf(ysq, 0.99f);
            const float A   = 1.0f + 2.0f * xy + ysc;
            const float B   = 1.0f - xsc;
            const float dn  = fmaxf(1.0f + 2.0f * xy + xsc * ysc, EPSF);
            const float cbg = (-STEPSZ * sc) * __fdividef(B, dn);  // coeff on grad
            alpha = __fdividef(A, dn) - cbg * slam;                // coeff on p
            beta  = cbg;                                           // coeff on G
            p_new = alpha * alpha * p_sq + 2.0f * alpha * beta * pG
                  + beta * beta * GG;
            const float rn = sqrtf(p_new);
            if (rn >= 1.0f - EPSF) {
                cf = __fdividef(1.0f - 2.0f * EPSF, rn);
                p_new *= cf * cf;
            }
        }
        p_sq = p_new;
        if (lane == 0)
            aux[16 + w] = cf * (alpha * aux[16 + w] + beta * xG);
        // next iteration's post-lam_mu sync orders the aux writes
    }

    // ---- final distances + violation (1 RED per CTA) ----
    if (lane == 0) {
        const float xs  = aux[w];
        const float dot = aux[16 + w];
        const float dsq = xs - 2.0f * dot + p_sq;
        const float den = fmaxf((1.0f - xs) * (1.0f - p_sq), EPSF);
        const float fr  = fmaxf(__fdividef(dsq, den), 0.0f);
        const float dd  = asinhf(sqrtf(fr));
        aux[80 + w] = fmaxf(dd - 2.0f, 0.0f);
    }
    __syncthreads();
    if (tid == 0) {
        float vi = 0.0f;
#pragma unroll
        for (int i = 0; i < NWARP; i++) vi += aux[80 + i];
        atomicAdd(&g_viol, vi);
    }
    __syncthreads();

    // ---- last-arriver writes output (no final grid barrier) ----
    if (tid == 0) {
        __threadfence();               // make own viol RED visible first
        const unsigned old = atomicAdd(&g_cnt, 1u);
        if (old == base + cnt * NBLK + (NBLK - 1u)) {
            __threadfence();           // acquire: all CTAs' viol REDs done
            out[0] = __ldcg(&g_viol) * (1.0f / (float)KTOK);
            g_viol = 0.0f;
            g_sc[0] = make_float4(0.f, 0.f, 0.f, 0.f);
            g_sc[1] = make_float4(0.f, 0.f, 0.f, 0.f);
        }
    }

    // ---- restore zeroed-on-exit invariant (dirty: g_m, banks buf 0 and 1) --
    if (tid < DSL) g_m[ds + tid] = 0.0f;
    if (tid < NBANK * DSL) {
        const int bk = tid / DSL;
        const int e  = ds + (tid & (DSL - 1));
        g_g[bk][0][e] = 0.0f;
        g_g[bk][1][e] = 0.0f;
    }
}

extern "C" void kernel_launch(void* const* d_in, const int* in_sizes, int n_in,
                              void* d_out, int out_size)
{
    (void)in_sizes; (void)n_in; (void)out_size;
    cudaFuncSetAttribute(traj_kernel,
                         cudaFuncAttributeMaxDynamicSharedMemorySize, SMEM_BYTES);
    const float *in = (const float *)d_in[0];
    float *out = (float *)d_out;
    traj_kernel<<<NBLK, NTHR, SMEM_BYTES>>>(in, out);
}